// round 11
// baseline (speedup 1.0000x reference)
#include <cuda_runtime.h>

#define NFEAT 17
#define NEV 16
#define PPE 65536
#define NPTS (NEV * PPE)
#define T_B 0.2f
#define R2C 0.49f

#define BPE 8                  // blocks per event (one 8192-row slice each)
#define SLICE (PPE / BPE)
#define PPT 8                  // register-resident points per thread
#define MAXI 64
#define CHROWS 2048            // rows per smem staging chunk
#define CHF4 (CHROWS * NFEAT / 4)   // 8704 float4 per chunk
#define NSLOT (NEV * MAXI * BPE)    // mailbox slots (4 u64 words each)

// ---- device scratch (no allocation allowed) ----
__device__ unsigned long long g_pub[NSLOT * 4];  // [key, xy, z, pad]
__device__ int g_ccnt[NEV];
__device__ int g_zero_cnt;
__device__ int g_done;

// ---------------------------------------------------------------------------
// K1: per-launch init — zero mailbox flags + counters (graph-replay safe).
// ---------------------------------------------------------------------------
__global__ void init_kernel() {
    const int gid = blockIdx.x * blockDim.x + threadIdx.x;
    if (gid < NSLOT) g_pub[gid * 4] = 0ULL;      // key/flag word only
    if (gid == 0) { g_zero_cnt = 0; g_done = 0; }
}

// ---------------------------------------------------------------------------
// K2: everything. 128 blocks x 1024 threads, single wave.
//  Phase 1: chunked coalesced load of this block's contiguous x-slice into
//           smem; extract (c14,c15,c16,beta=c9) into registers p[PPT].
//  Phase 2: greedy condensation; per-iteration register pass; cross-block
//           exchange via mailbox (data words, fence, key-as-flag).
//           Key=(beta_bits<<32)|~row -> max = (max beta, min idx) = jnp.argmax.
//  Phase 3: cooperative zero of the 71MB output.
//  Phase 4: global barrier (zero complete), then sub0 blocks scatter rows,
//           last-done event writes row_splits.
// ---------------------------------------------------------------------------
__global__ void __launch_bounds__(1024, 1)
mega_kernel(const float* __restrict__ x, float* __restrict__ out,
            long long n, long long splits_off, int do_splits) {
    extern __shared__ float s[];                 // CHROWS*NFEAT floats

    __shared__ unsigned long long swk[32];
    __shared__ float swx[32], swy[32], swz[32];
    __shared__ unsigned long long s_key;
    __shared__ float s_cx, s_cy, s_cz;
    __shared__ int s_rows[MAXI];

    const int blk  = blockIdx.x;
    const int e    = blk / BPE;
    const int sub  = blk - e * BPE;
    const int t    = threadIdx.x;
    const int lane = t & 31;
    const int warp = t >> 5;
    const int base = e * PPE + sub * SLICE;

    // ================= Phase 1: load slice, extract to registers ===========
    float4 p[PPT];
    unsigned long long bk = 0ULL;
    float bx = 0.f, by = 0.f, bz = 0.f;

    const float4* xv = reinterpret_cast<const float4*>(x);
    const long long g0 = ((long long)base * NFEAT) >> 2;   // slice float4 start

    #pragma unroll
    for (int c = 0; c < SLICE / CHROWS; ++c) {
        // coalesced chunk load (contiguous bytes)
        const long long cg = g0 + (long long)c * CHF4;
        for (int v = t; v < CHF4; v += 1024)
            reinterpret_cast<float4*>(s)[v] = xv[cg + v];
        __syncthreads();
        // extract 2 rows per thread
        #pragma unroll
        for (int j = 0; j < 2; ++j) {
            const int lr = t + (j << 10);            // local row in chunk
            const int k  = 2 * c + j;                // register slot
            const int i  = base + t + (k << 10);     // global row (consistent)
            const float* srow = s + lr * NFEAT;
            p[k].x = srow[14];
            p[k].y = srow[15];
            p[k].z = srow[16];
            p[k].w = srow[9];
            if (p[k].w >= T_B) {
                const unsigned long long key =
                    ((unsigned long long)__float_as_uint(p[k].w) << 32) |
                    (unsigned)(~(unsigned)i);
                if (key > bk) { bk = key; bx = p[k].x; by = p[k].y; bz = p[k].z; }
            } else {
                p[k].w = -1.0f;
            }
        }
        __syncthreads();
    }

    // ================= Phase 2: greedy condensation =========================
    int count = 0;
    for (int it = 0; it < MAXI; ++it) {
        // warp argmax of (key, coords)
        #pragma unroll
        for (int off = 16; off > 0; off >>= 1) {
            const unsigned long long ok = __shfl_down_sync(0xFFFFFFFFu, bk, off);
            const float ox = __shfl_down_sync(0xFFFFFFFFu, bx, off);
            const float oy = __shfl_down_sync(0xFFFFFFFFu, by, off);
            const float oz = __shfl_down_sync(0xFFFFFFFFu, bz, off);
            if (ok > bk) { bk = ok; bx = ox; by = oy; bz = oz; }
        }
        if (lane == 0) { swk[warp] = bk; swx[warp] = bx; swy[warp] = by; swz[warp] = bz; }
        __syncthreads();
        if (warp == 0) {
            unsigned long long v = swk[lane];
            float vx = swx[lane], vy = swy[lane], vz = swz[lane];
            #pragma unroll
            for (int off = 16; off > 0; off >>= 1) {
                const unsigned long long ok = __shfl_down_sync(0xFFFFFFFFu, v, off);
                const float ox = __shfl_down_sync(0xFFFFFFFFu, vx, off);
                const float oy = __shfl_down_sync(0xFFFFFFFFu, vy, off);
                const float oz = __shfl_down_sync(0xFFFFFFFFu, vz, off);
                if (ok > v) { v = ok; vx = ox; vy = oy; vz = oz; }
            }
            // publish own winner: data words, fence, key flag
            if (lane == 0) {
                volatile unsigned long long* own =
                    g_pub + ((e * MAXI + it) * BPE + sub) * 4;
                own[1] = ((unsigned long long)__float_as_uint(vx) << 32) |
                         __float_as_uint(vy);
                own[2] = (unsigned long long)__float_as_uint(vz);
                __threadfence();
                own[0] = v ? v : 1ULL;               // sentinel for empty block
            }
            __syncwarp();
            // poll all 8 peer slots in parallel (lanes 0..7)
            unsigned long long pk = 0ULL, pxy = 0ULL, pzz = 0ULL;
            if (lane < 8) {
                volatile unsigned long long* sl =
                    g_pub + ((e * MAXI + it) * BPE + lane) * 4;
                while ((pk = sl[0]) == 0ULL) { }
                pxy = sl[1];
                pzz = sl[2];
            }
            #pragma unroll
            for (int off = 4; off > 0; off >>= 1) {
                const unsigned long long ok  = __shfl_down_sync(0xFFFFFFFFu, pk,  off);
                const unsigned long long oxy = __shfl_down_sync(0xFFFFFFFFu, pxy, off);
                const unsigned long long ozz = __shfl_down_sync(0xFFFFFFFFu, pzz, off);
                if (ok > pk) { pk = ok; pxy = oxy; pzz = ozz; }
            }
            if (lane == 0) {
                s_key = pk;
                s_cx = __uint_as_float((unsigned)(pxy >> 32));
                s_cy = __uint_as_float((unsigned)pxy);
                s_cz = __uint_as_float((unsigned)pzz);
            }
        }
        __syncthreads();

        const unsigned long long wk = s_key;
        const float wb = __uint_as_float((unsigned)(wk >> 32));
        if (wb < T_B) break;

        if (t == 0) s_rows[count] = (int)(~(unsigned)(wk & 0xFFFFFFFFull));
        ++count;

        const float cx = s_cx, cy = s_cy, cz = s_cz;

        // register pass: suppress + next per-thread (key, coords)
        bk = 0ULL;
        #pragma unroll
        for (int k = 0; k < PPT; ++k) {
            const float w = p[k].w;
            if (w >= 0.0f) {
                const float dx = p[k].x - cx;
                const float dy = p[k].y - cy;
                const float dz = p[k].z - cz;
                if (dx * dx + dy * dy + dz * dz <= R2C) {
                    p[k].w = -1.0f;
                } else {
                    const int i = base + t + (k << 10);
                    const unsigned long long key =
                        ((unsigned long long)__float_as_uint(w) << 32) |
                        (unsigned)(~(unsigned)i);
                    if (key > bk) { bk = key; bx = p[k].x; by = p[k].y; bz = p[k].z; }
                }
            }
        }
    }

    // ================= Phase 3: cooperative zero of output ==================
    {
        const long long gid    = (long long)blk * 1024 + t;
        const long long stride = 128LL * 1024;
        const long long n4 = n >> 2;
        float4 z; z.x = 0.f; z.y = 0.f; z.z = 0.f; z.w = 0.f;
        for (long long j = gid; j < n4; j += stride)
            reinterpret_cast<float4*>(out)[j] = z;
        if (gid < (n & 3)) out[(n4 << 2) + gid] = 0.f;
    }
    // release: every thread's stores, then one arrival per block
    __threadfence();
    __syncthreads();
    if (t == 0) atomicAdd(&g_zero_cnt, 1);

    // ================= Phase 4: scatter + splits (sub 0 blocks) =============
    if (sub == 0) {
        if (t == 0) {
            volatile int* vc = &g_zero_cnt;
            while (*vc < NEV * BPE) { __nanosleep(128); }
            __threadfence();   // acquire
        }
        __syncthreads();

        for (int c = warp; c < count; c += 32) {
            const long long row = (long long)s_rows[c];
            if (lane < NFEAT)
                out[row * NFEAT + lane] = x[row * NFEAT + lane];
        }
        __syncthreads();
        if (t == 0) {
            *(volatile int*)&g_ccnt[e] = count;
            __threadfence();
            if (do_splits) {
                const int old = atomicAdd(&g_done, 1);
                if (old == NEV - 1) {
                    __threadfence();
                    int acc = 0;
                    out[splits_off] = 0.0f;
                    #pragma unroll
                    for (int ev = 0; ev < NEV; ++ev) {
                        acc += *(volatile int*)&g_ccnt[ev];
                        out[splits_off + 1 + ev] = (float)acc;
                    }
                }
            }
        }
    }
}

// ---------------------------------------------------------------------------
extern "C" void kernel_launch(void* const* d_in, const int* in_sizes, int n_in,
                              void* d_out, int out_size) {
    const float* x   = (const float*)d_in[0];
    float*       out = (float*)d_out;
    const long long n = (long long)out_size;

    static const size_t dyn_smem = (size_t)CHROWS * NFEAT * sizeof(float); // 139264
    cudaFuncSetAttribute(mega_kernel,
                         cudaFuncAttributeMaxDynamicSharedMemorySize,
                         (int)dyn_smem);

    // K1: reset mailbox flags + counters (graph-replay safe)
    init_kernel<<<(NSLOT + 1023) / 1024, 1024>>>();

    // K2: load + condense + zero + scatter + splits, single wave
    const long long dout_elems = (long long)NPTS * NFEAT;
    const int do_splits = (n == dout_elems + NEV + 1) ? 1 : 0;
    mega_kernel<<<NEV * BPE, 1024, dyn_smem>>>(x, out, n, dout_elems, do_splits);
}

// round 12
// speedup vs baseline: 1.6055x; 1.6055x over previous
#include <cuda_runtime.h>

#define NFEAT 17
#define NEV 16
#define PPE 65536
#define NPTS (NEV * PPE)
#define T_B 0.2f
#define R2C 0.49f

#define BPE 8                 // blocks per event (one 8192-pt slice each)
#define SLICE (PPE / BPE)
#define PPT 8                 // points per thread, register-resident
#define MAXI 64
#define NKEY (NEV * MAXI * BPE)

// ---- device scratch (no allocation allowed) ----
__device__ float4             g_pts[NPTS];   // (x,y,z,beta)
__device__ unsigned long long g_key[NKEY];   // mailbox: one u64 key per block/iter
__device__ int                g_ccnt[NEV];
__device__ int                g_done;

// ---------------------------------------------------------------------------
// K1: zero output (STREAMING stores — keep g_pts resident in L2) + pack pts
//     + zero mailbox/done counter.
// ---------------------------------------------------------------------------
__global__ void zero_pack_kernel(const float* __restrict__ x,
                                 float* __restrict__ out, long long n) {
    const long long gid    = (long long)blockIdx.x * blockDim.x + threadIdx.x;
    const long long stride = (long long)gridDim.x * blockDim.x;

    const long long n4 = n >> 2;
    const float4 z = make_float4(0.f, 0.f, 0.f, 0.f);
    for (long long j = gid; j < n4; j += stride)
        __stcs(reinterpret_cast<float4*>(out) + j, z);   // evict-first
    if (gid < (n & 3)) __stcs(out + (n4 << 2) + gid, 0.f);

    if (gid < NKEY) g_key[gid] = 0ULL;
    if (gid == 0)   g_done = 0;

    if (gid < NPTS) {
        const float* r = x + gid * NFEAT;
        float4 p;
        p.x = __ldcs(r + 14);      // streaming reads: x is read-once here
        p.y = __ldcs(r + 15);
        p.z = __ldcs(r + 16);
        p.w = __ldcs(r + 9);
        g_pts[gid] = p;            // normal store: stays hot in L2
    }
}

// ---------------------------------------------------------------------------
// K2: condensation + scatter + splits. 8 blocks/event, 1024 thr, single wave.
//   Candidates REGISTER-resident (p[8]); suppression sets w=-1.
//   Key = (beta_bits<<32)|(~row): max key == (max beta, min idx) == jnp.argmax.
//   Exchange: 8B volatile key store (atomic, key-as-flag, fresh slot/iter);
//   lanes 0..7 poll the 8 slots AND speculatively load their slot's candidate
//   coords in parallel; (key,coords) reduced together — no dependent load.
// ---------------------------------------------------------------------------
__global__ void __launch_bounds__(1024, 1)
condense_kernel(const float* __restrict__ x, float* __restrict__ out,
                long long splits_off, int do_splits) {
    __shared__ unsigned long long swk[32];
    __shared__ unsigned long long s_key;
    __shared__ float s_cx, s_cy, s_cz;
    __shared__ int s_rows[MAXI];

    const int blk  = blockIdx.x;
    const int e    = blk / BPE;
    const int sub  = blk - e * BPE;
    const int t    = threadIdx.x;
    const int lane = t & 31;
    const int warp = t >> 5;
    const int base = e * PPE + sub * SLICE;

    // ---- load slice into registers + initial per-thread argmax key ----
    float4 p[PPT];
    unsigned long long bk = 0ULL;
    #pragma unroll
    for (int k = 0; k < PPT; ++k) {
        const int i = base + t + (k << 10);
        p[k] = g_pts[i];
        if (p[k].w >= T_B) {
            const unsigned long long key =
                ((unsigned long long)__float_as_uint(p[k].w) << 32) |
                (unsigned)(~(unsigned)i);
            if (key > bk) bk = key;
        } else {
            p[k].w = -1.0f;
        }
    }

    int count = 0;

    for (int it = 0; it < MAXI; ++it) {
        // ---- block argmax of keys ----
        #pragma unroll
        for (int off = 16; off > 0; off >>= 1) {
            const unsigned long long o = __shfl_down_sync(0xFFFFFFFFu, bk, off);
            if (o > bk) bk = o;
        }
        if (lane == 0) swk[warp] = bk;
        __syncthreads();
        if (warp == 0) {
            unsigned long long v = swk[lane];
            #pragma unroll
            for (int off = 16; off > 0; off >>= 1) {
                const unsigned long long o = __shfl_down_sync(0xFFFFFFFFu, v, off);
                if (o > v) v = o;
            }
            // ---- publish own key (8B volatile store = atomic, flag!=0) ----
            if (lane == 0) {
                const unsigned long long pubk = v ? v : 1ULL;
                unsigned long long* own = g_key + (e * MAXI + it) * BPE + sub;
                asm volatile("st.volatile.global.b64 [%0], %1;"
                             :: "l"(own), "l"(pubk) : "memory");
            }
            __syncwarp();
            // ---- poll the 8 slots + speculative coord load per lane ----
            unsigned long long pk = 0ULL;
            float px = 0.f, py = 0.f, pz = 0.f;
            if (lane < 8) {
                const unsigned long long* sl = g_key + (e * MAXI + it) * BPE + lane;
                do {
                    asm volatile("ld.volatile.global.b64 %0, [%1];"
                                 : "=l"(pk) : "l"(sl));
                } while (pk == 0ULL);
                if (pk != 1ULL) {
                    const int row = (int)(~(unsigned)(pk & 0xFFFFFFFFull));
                    const float4 rp = g_pts[row];   // 8 parallel L2 loads
                    px = rp.x; py = rp.y; pz = rp.z;
                }
            }
            #pragma unroll
            for (int off = 4; off > 0; off >>= 1) {
                const unsigned long long ok = __shfl_down_sync(0xFFFFFFFFu, pk, off);
                const float ox = __shfl_down_sync(0xFFFFFFFFu, px, off);
                const float oy = __shfl_down_sync(0xFFFFFFFFu, py, off);
                const float oz = __shfl_down_sync(0xFFFFFFFFu, pz, off);
                if (ok > pk) { pk = ok; px = ox; py = oy; pz = oz; }
            }
            if (lane == 0) {
                s_key = pk;
                s_cx = px; s_cy = py; s_cz = pz;
            }
        }
        __syncthreads();

        const unsigned long long wk = s_key;
        const float wb = __uint_as_float((unsigned)(wk >> 32));
        if (wb < T_B) break;

        if (t == 0) s_rows[count] = (int)(~(unsigned)(wk & 0xFFFFFFFFull));
        ++count;

        const float cx = s_cx, cy = s_cy, cz = s_cz;

        // ---- register pass: suppress + next per-thread key ----
        bk = 0ULL;
        #pragma unroll
        for (int k = 0; k < PPT; ++k) {
            const float w = p[k].w;
            if (w >= 0.0f) {
                const float dx = p[k].x - cx;
                const float dy = p[k].y - cy;
                const float dz = p[k].z - cz;
                if (dx * dx + dy * dy + dz * dz <= R2C) {
                    p[k].w = -1.0f;
                } else {
                    const int i = base + t + (k << 10);
                    const unsigned long long key =
                        ((unsigned long long)__float_as_uint(w) << 32) |
                        (unsigned)(~(unsigned)i);
                    if (key > bk) bk = key;
                }
            }
        }
    }

    // ---- tail: scatter this event's rows (sub 0) + splits (last event) ----
    __syncthreads();
    if (sub == 0) {
        for (int c = warp; c < count; c += 32) {
            const long long row = (long long)s_rows[c];
            if (lane < NFEAT)
                out[row * NFEAT + lane] = x[row * NFEAT + lane];
        }
        if (t == 0) {
            *(volatile int*)&g_ccnt[e] = count;
            __threadfence();
            if (do_splits) {
                const int old = atomicAdd(&g_done, 1);
                if (old == NEV - 1) {
                    __threadfence();
                    int acc = 0;
                    out[splits_off] = 0.0f;
                    #pragma unroll
                    for (int ev = 0; ev < NEV; ++ev) {
                        acc += *(volatile int*)&g_ccnt[ev];
                        out[splits_off + 1 + ev] = (float)acc;
                    }
                }
            }
        }
    }
}

// ---------------------------------------------------------------------------
extern "C" void kernel_launch(void* const* d_in, const int* in_sizes, int n_in,
                              void* d_out, int out_size) {
    const float* x   = (const float*)d_in[0];
    float*       out = (float*)d_out;
    const long long n = (long long)out_size;

    // 1) fused zero(streaming) + pack + mailbox init
    zero_pack_kernel<<<NPTS / 256, 256>>>(x, out, n);

    // 2) condense + scatter + splits (128 blocks: single wave, poll-safe)
    const long long dout_elems = (long long)NPTS * NFEAT;
    const int do_splits = (n == dout_elems + NEV + 1) ? 1 : 0;
    condense_kernel<<<NEV * BPE, 1024>>>(x, out, dout_elems, do_splits);
}